// round 3
// baseline (speedup 1.0000x reference)
#include <cuda_runtime.h>
#include <math.h>

// Problem constants
#define HID   1024
#define NEXP  64
#define NTOK  262144
#define NA    (NTOK * 2)          // 524288 assignments
#define SEGS  (NA / 32)           // 16384 warp-segments
#define CAP   10240               // int(N*K/E * 1.25)

// GEMM tile config
#define MT       128              // tokens per block
#define KC       32               // K chunk
#define NTHREADS 256

// ---------------- scratch (device globals: allocation-free) ----------------
__device__ int   g_idx[NA];               // top-k expert indices, flat (token,k)
__device__ float g_w[NA];                 // pre-mask normalized top-k weights
__device__ int   g_hist[NEXP * SEGS];     // per-(expert, warp-segment) counts -> exclusive bases
__device__ int   g_total[NEXP];           // per-expert total assignment count

// ---------------- packed fp32x2 helpers (sm_103a FFMA2) ----------------
__device__ __forceinline__ unsigned long long ffma2(unsigned long long a,
                                                    unsigned long long b,
                                                    unsigned long long c) {
    unsigned long long d;
    asm("fma.rn.f32x2 %0, %1, %2, %3;" : "=l"(d) : "l"(a), "l"(b), "l"(c));
    return d;
}
__device__ __forceinline__ unsigned long long pack2(float x) {
    unsigned long long d;
    asm("mov.b64 %0, {%1, %1};" : "=l"(d) : "f"(x));
    return d;
}
__device__ __forceinline__ void unpack2(unsigned long long v, float& lo, float& hi) {
    asm("mov.b64 {%0, %1}, %2;" : "=f"(lo), "=f"(hi) : "l"(v));
}

// ============================================================================
// K1: gating GEMM (x @ W) + fused softmax/top-2 epilogue.
// Block: 128 tokens x 64 experts. Thread (te = tid&7 expert-group, tt = tid>>3
// token-group) owns 4 tokens {tt, tt+32, tt+64, tt+96} x 8 experts [8*te, 8*te+8).
// A token's 64 experts live in 8 consecutive lanes -> shfl-xor top-2 reduce.
// ============================================================================
__global__ __launch_bounds__(NTHREADS)
void k_gemm_top2(const float* __restrict__ x, const float* __restrict__ W,
                 float* __restrict__ out) {
    __shared__ float xs[MT * 36];     // [token][kk], pitch 36 (pad; 16B-aligned rows)
    __shared__ float ws[KC * 64];     // [kk][expert]

    const int tid  = threadIdx.x;
    const int tok0 = blockIdx.x * MT;
    const int te   = tid & 7;         // expert group
    const int tt   = tid >> 3;        // token group (0..31)
    const int e0   = te * 8;

    unsigned long long acc[4][4];
    #pragma unroll
    for (int j = 0; j < 4; j++)
        #pragma unroll
        for (int p = 0; p < 4; p++) acc[j][p] = 0ull;

    const float4* x4 = (const float4*)x;
    const float4* w4 = (const float4*)W;

    for (int kb = 0; kb < HID; kb += KC) {
        // Stage x chunk: 128 tokens x 32 cols = 1024 float4, 4 per thread (coalesced).
        #pragma unroll
        for (int r = 0; r < 4; r++) {
            int idx = r * NTHREADS + tid;
            int t   = idx >> 3;
            int c4  = idx & 7;
            float4 v = x4[(size_t)(tok0 + t) * (HID / 4) + (kb >> 2) + c4];
            *(float4*)&xs[t * 36 + c4 * 4] = v;
        }
        // Stage W chunk: 32 rows x 64 experts = 512 float4, 2 per thread.
        #pragma unroll
        for (int r = 0; r < 2; r++) {
            int idx = r * NTHREADS + tid;
            int row = idx >> 4;
            int c4  = idx & 15;
            ((float4*)ws)[row * 16 + c4] = w4[(size_t)(kb + row) * (NEXP / 4) + c4];
        }
        __syncthreads();

        #pragma unroll
        for (int kk = 0; kk < KC; kk++) {
            unsigned long long wv[4];
            const unsigned long long* wrow =
                (const unsigned long long*)(ws + kk * 64 + e0);
            #pragma unroll
            for (int p = 0; p < 4; p++) wv[p] = wrow[p];   // LDS.64, warp-broadcast
            #pragma unroll
            for (int j = 0; j < 4; j++) {
                unsigned long long xx = pack2(xs[(tt + 32 * j) * 36 + kk]);
                #pragma unroll
                for (int p = 0; p < 4; p++) acc[j][p] = ffma2(xx, wv[p], acc[j][p]);
            }
        }
        __syncthreads();
    }

    // Epilogue: per-token top-2 with jax.lax.top_k tie rules (value desc, index asc).
    #pragma unroll
    for (int j = 0; j < 4; j++) {
        float b0 = -3.4e38f, b1 = -3.4e38f;
        int   c0 = 0,        c1 = 0;
        #pragma unroll
        for (int p = 0; p < 4; p++) {
            float lo, hi;
            unpack2(acc[j][p], lo, hi);
            int el = e0 + 2 * p, eh = el + 1;
            if (lo > b0)      { b1 = b0; c1 = c0; b0 = lo; c0 = el; }
            else if (lo > b1) { b1 = lo; c1 = el; }
            if (hi > b0)      { b1 = b0; c1 = c0; b0 = hi; c0 = eh; }
            else if (hi > b1) { b1 = hi; c1 = eh; }
        }
        // butterfly merge across the 8 expert-group lanes
        #pragma unroll
        for (int off = 1; off < 8; off <<= 1) {
            float ov0 = __shfl_xor_sync(0xffffffffu, b0, off);
            int   oc0 = __shfl_xor_sync(0xffffffffu, c0, off);
            float ov1 = __shfl_xor_sync(0xffffffffu, b1, off);
            int   oc1 = __shfl_xor_sync(0xffffffffu, c1, off);
            bool bFirst = (ov0 > b0) || (ov0 == b0 && oc0 < c0);
            float n0, n1; int m0, m1;
            if (bFirst) {
                n0 = ov0; m0 = oc0;
                bool aBeatsB1 = (b0 > ov1) || (b0 == ov1 && c0 < oc1);
                if (aBeatsB1) { n1 = b0;  m1 = c0;  } else { n1 = ov1; m1 = oc1; }
            } else {
                n0 = b0; m0 = c0;
                bool bBeatsA1 = (ov0 > b1) || (ov0 == b1 && oc0 < c1);
                if (bBeatsA1) { n1 = ov0; m1 = oc0; } else { n1 = b1;  m1 = c1;  }
            }
            b0 = n0; c0 = m0; b1 = n1; c1 = m1;
        }
        if (te == 0) {
            int t = tok0 + tt + 32 * j;
            // weights: p0/(p0+p1) = 1/(1+exp(l1-l0)); exact algebraic match to ref
            float ex = expf(b1 - b0);
            float w0 = 1.0f / (1.0f + ex);
            float w1 = ex * w0;
            g_idx[2 * t]     = c0;
            g_idx[2 * t + 1] = c1;
            g_w[2 * t]       = w0;
            g_w[2 * t + 1]   = w1;
            out[2 * t]     = (float)c0;      // top_k_indices segment (as f32)
            out[2 * t + 1] = (float)c1;
        }
    }
}

// ============================================================================
// K0: zero the histogram (coalesced).
// ============================================================================
__global__ void k_zero_hist() {
    int i = blockIdx.x * blockDim.x + threadIdx.x;
    g_hist[i] = 0;
}

// ============================================================================
// K2: per-warp-segment expert histogram. Warp g owns assignments [32g, 32g+32);
// lane order == assignment order, so warp-local ranks are order-exact.
// ============================================================================
__global__ void k_count() {
    int i    = blockIdx.x * blockDim.x + threadIdx.x;   // assignment index
    int lane = threadIdx.x & 31;
    int g    = i >> 5;
    int e    = g_idx[i];
    unsigned peers = __match_any_sync(0xffffffffu, e);
    unsigned lt    = (1u << lane) - 1u;
    if ((peers & lt) == 0u)                              // leader of its expert group
        g_hist[e * SEGS + g] = __popc(peers);
}

// ============================================================================
// K-scan: per expert (one block each), exclusive scan over 16384 segments,
// in-place (hist -> exclusive base). Also emits per-expert totals.
// ============================================================================
__global__ void k_scan() {
    __shared__ int s[256];
    const int e   = blockIdx.x;
    const int tid = threadIdx.x;
    int carry = 0;
    for (int c = 0; c < SEGS; c += 256) {
        int v = g_hist[e * SEGS + c + tid];
        s[tid] = v;
        __syncthreads();
        int xsum = v;
        #pragma unroll
        for (int off = 1; off < 256; off <<= 1) {
            int t = (tid >= off) ? s[tid - off] : 0;
            __syncthreads();
            xsum += t;
            s[tid] = xsum;
            __syncthreads();
        }
        g_hist[e * SEGS + c + tid] = carry + xsum - v;   // exclusive + carry
        int tot = s[255];
        __syncthreads();
        carry += tot;
    }
    if (tid == 0) g_total[e] = carry;
}

// ============================================================================
// K3: final mask + renormalized weights. pos = segment base + warp-local rank.
// Lanes (2t, 2t+1) are a token's two assignments -> shfl_xor(1) gives mask_sum.
// ============================================================================
__global__ void k_mask(float* __restrict__ out) {
    int i    = blockIdx.x * blockDim.x + threadIdx.x;
    int lane = threadIdx.x & 31;
    int g    = i >> 5;
    int e    = g_idx[i];
    unsigned peers = __match_any_sync(0xffffffffu, e);
    unsigned lt    = (1u << lane) - 1u;
    int pos = g_hist[e * SEGS + g] + __popc(peers & lt);
    float m  = (pos < CAP) ? 1.0f : 0.0f;
    float mo = __shfl_xor_sync(0xffffffffu, m, 1);
    float w  = g_w[i];
    out[NA + i]     = w * m / (m + mo + 1e-10f);   // top_k_weights segment
    out[2 * NA + i] = m;                            // capacity_mask segment
}

// ============================================================================
// K4: expert_counters (min(total, cap)) and num_dropped.
// ============================================================================
__global__ void k_stats(float* __restrict__ out) {
    __shared__ int sdrop[NEXP];
    int e    = threadIdx.x;
    int tot  = g_total[e];
    int kept = min(tot, CAP);
    out[3 * NA + e] = (float)kept;                  // expert_counters segment
    sdrop[e] = tot - kept;
    __syncthreads();
    if (e == 0) {
        int s = 0;
        #pragma unroll
        for (int i = 0; i < NEXP; i++) s += sdrop[i];
        out[3 * NA + NEXP] = (float)s;              // num_dropped
    }
}

// ============================================================================
extern "C" void kernel_launch(void* const* d_in, const int* in_sizes, int n_in,
                              void* d_out, int out_size) {
    const float* x = (const float*)d_in[0];   // [N, 1024]
    const float* W = (const float*)d_in[1];   // [1024, 64]
    float* out = (float*)d_out;

    k_gemm_top2<<<NTOK / MT, NTHREADS>>>(x, W, out);
    k_zero_hist<<<(NEXP * SEGS) / 256, 256>>>();
    k_count<<<NA / 256, 256>>>();
    k_scan<<<NEXP, 256>>>();
    k_mask<<<NA / 256, 256>>>(out);
    k_stats<<<1, NEXP>>>(out);
}

// round 6
// speedup vs baseline: 1.3147x; 1.3147x over previous
#include <cuda_runtime.h>
#include <math.h>

// Problem constants
#define HID   1024
#define NEXP  64
#define NTOK  262144
#define NA    (NTOK * 2)          // 524288 assignments
#define CAP   10240               // int(N*K/E * 1.25)

// GEMM tile config
#define MT       256              // tokens per block
#define KC       16               // K chunk
#define NTHREADS 256
#define NBLK     (NTOK / MT)      // 1024 GEMM blocks == histogram segments
#define XPITCH   17               // float2 pitch per token row (pad)

// ---------------- scratch (device globals: allocation-free) ----------------
__device__ int   g_idx[NA];               // top-k expert indices, flat (token,k)
__device__ float g_w[NA];                 // pre-mask normalized top-k weights
__device__ int   g_hist[NEXP * NBLK];     // per-(expert, block-segment) counts -> exclusive bases
__device__ int   g_total[NEXP];           // per-expert total assignment count

// ---------------- packed fp32x2 helpers (sm_103a FFMA2) ----------------
__device__ __forceinline__ unsigned long long ffma2(unsigned long long a,
                                                    unsigned long long b,
                                                    unsigned long long c) {
    unsigned long long d;
    asm("fma.rn.f32x2 %0, %1, %2, %3;" : "=l"(d) : "l"(a), "l"(b), "l"(c));
    return d;
}
__device__ __forceinline__ void unpack2(unsigned long long v, float& lo, float& hi) {
    asm("mov.b64 {%0, %1}, %2;" : "=f"(lo), "=f"(hi) : "l"(v));
}

// ============================================================================
// K1: gating GEMM (x @ W) + fused softmax/top-2 epilogue + per-block expert
// histogram.
// Block: 256 tokens x 64 experts, 256 threads.
// Thread (te = tid&7, tt = tid>>3) owns 8 tokens {tt + 32j} x 8 experts
// [8te, 8te+8). x is staged DUPLICATED as float2 in smem so the inner loop is
// pure LDS.64 + FFMA2 (no pack movs). Next chunk is prefetched into registers.
// ============================================================================
__global__ __launch_bounds__(NTHREADS, 2)
void k_gemm_top2(const float* __restrict__ x, const float* __restrict__ W,
                 float* __restrict__ out) {
    __shared__ float2 xs[MT * XPITCH];    // x dup'd: [token][kk] as (v,v)
    __shared__ float  ws[KC * NEXP];      // [kk][expert]
    __shared__ int    hist[NEXP];

    const int tid  = threadIdx.x;
    const int tok0 = blockIdx.x * MT;
    const int te   = tid & 7;
    const int tt   = tid >> 3;
    const int e0   = te * 8;

    if (tid < NEXP) hist[tid] = 0;

    unsigned long long acc[8][4];
    #pragma unroll
    for (int j = 0; j < 8; j++)
        #pragma unroll
        for (int p = 0; p < 4; p++) acc[j][p] = 0ull;

    const float4* x4 = (const float4*)x;
    const float4* w4 = (const float4*)W;

    // thread's staging coordinates (x): 1024 float4 per chunk, 4 per thread
    // idx = r*256 + tid -> token = idx>>2, c4 = idx&3 (4 float4 per token row)
    // prefetch chunk 0
    float4 px[4];
    #pragma unroll
    for (int r = 0; r < 4; r++) {
        int idx = r * NTHREADS + tid;
        px[r] = x4[(size_t)(tok0 + (idx >> 2)) * (HID / 4) + (idx & 3)];
    }
    float4 pw = w4[(size_t)(tid >> 4) * (NEXP / 4) + (tid & 15)];

    for (int kb = 0; kb < HID; kb += KC) {
        __syncthreads();   // previous chunk's compute done; smem reusable
        // store prefetched x (duplicated) and w
        #pragma unroll
        for (int r = 0; r < 4; r++) {
            int idx = r * NTHREADS + tid;
            int t   = idx >> 2;
            int c4  = idx & 3;
            float2* dst = &xs[t * XPITCH + c4 * 4];
            dst[0] = make_float2(px[r].x, px[r].x);
            dst[1] = make_float2(px[r].y, px[r].y);
            dst[2] = make_float2(px[r].z, px[r].z);
            dst[3] = make_float2(px[r].w, px[r].w);
        }
        ((float4*)ws)[tid] = pw;   // 16 rows x 16 float4
        __syncthreads();

        // prefetch next chunk while computing this one
        if (kb + KC < HID) {
            #pragma unroll
            for (int r = 0; r < 4; r++) {
                int idx = r * NTHREADS + tid;
                px[r] = x4[(size_t)(tok0 + (idx >> 2)) * (HID / 4)
                           + ((kb + KC) >> 2) + (idx & 3)];
            }
            pw = w4[(size_t)(kb + KC + (tid >> 4)) * (NEXP / 4) + (tid & 15)];
        }

        #pragma unroll
        for (int kk = 0; kk < KC; kk++) {
            unsigned long long wv[4];
            const unsigned long long* wrow =
                (const unsigned long long*)(ws + kk * NEXP + e0);
            #pragma unroll
            for (int p = 0; p < 4; p++) wv[p] = wrow[p];
            #pragma unroll
            for (int j = 0; j < 8; j++) {
                unsigned long long xx =
                    *(const unsigned long long*)&xs[(tt + 32 * j) * XPITCH + kk];
                #pragma unroll
                for (int p = 0; p < 4; p++) acc[j][p] = ffma2(xx, wv[p], acc[j][p]);
            }
        }
    }

    // Epilogue: per-token top-2 (jax tie rules: value desc, index asc),
    // weights, index outputs, and block expert histogram.
    #pragma unroll
    for (int j = 0; j < 8; j++) {
        float b0 = -3.4e38f, b1 = -3.4e38f;
        int   c0 = 0,        c1 = 0;
        #pragma unroll
        for (int p = 0; p < 4; p++) {
            float lo, hi;
            unpack2(acc[j][p], lo, hi);
            int el = e0 + 2 * p, eh = el + 1;
            if (lo > b0)      { b1 = b0; c1 = c0; b0 = lo; c0 = el; }
            else if (lo > b1) { b1 = lo; c1 = el; }
            if (hi > b0)      { b1 = b0; c1 = c0; b0 = hi; c0 = eh; }
            else if (hi > b1) { b1 = hi; c1 = eh; }
        }
        #pragma unroll
        for (int off = 1; off < 8; off <<= 1) {
            float ov0 = __shfl_xor_sync(0xffffffffu, b0, off);
            int   oc0 = __shfl_xor_sync(0xffffffffu, c0, off);
            float ov1 = __shfl_xor_sync(0xffffffffu, b1, off);
            int   oc1 = __shfl_xor_sync(0xffffffffu, c1, off);
            bool bFirst = (ov0 > b0) || (ov0 == b0 && oc0 < c0);
            float n0, n1; int m0, m1;
            if (bFirst) {
                n0 = ov0; m0 = oc0;
                bool aBeatsB1 = (b0 > ov1) || (b0 == ov1 && c0 < oc1);
                if (aBeatsB1) { n1 = b0;  m1 = c0;  } else { n1 = ov1; m1 = oc1; }
            } else {
                n0 = b0; m0 = c0;
                bool bBeatsA1 = (ov0 > b1) || (ov0 == b1 && oc0 < c1);
                if (bBeatsA1) { n1 = ov0; m1 = oc0; } else { n1 = b1;  m1 = c1;  }
            }
            b0 = n0; c0 = m0; b1 = n1; c1 = m1;
        }
        if (te == 0) {
            int t = tok0 + tt + 32 * j;
            float ex = expf(b1 - b0);
            float w0 = 1.0f / (1.0f + ex);     // p0/(p0+p1), algebraically exact
            float w1 = ex * w0;
            g_idx[2 * t]     = c0;
            g_idx[2 * t + 1] = c1;
            g_w[2 * t]       = w0;
            g_w[2 * t + 1]   = w1;
            out[2 * t]     = (float)c0;        // top_k_indices segment
            out[2 * t + 1] = (float)c1;
            atomicAdd(&hist[c0], 1);
            atomicAdd(&hist[c1], 1);
        }
    }
    __syncthreads();
    if (tid < NEXP) g_hist[tid * NBLK + blockIdx.x] = hist[tid];
}

// ============================================================================
// K-scan: per expert (64 blocks), exclusive scan over NBLK=1024 segment counts,
// in-place. shfl-based warp scans (no Hillis-Steele smem ping-pong).
// ============================================================================
__global__ void k_scan() {
    __shared__ int warpsum[8];
    const int e    = blockIdx.x;
    const int tid  = threadIdx.x;
    const int lane = tid & 31;
    const int w    = tid >> 5;
    int carry = 0;
    for (int c = 0; c < NBLK; c += 256) {
        int v = g_hist[e * NBLK + c + tid];
        int s = v;
        #pragma unroll
        for (int off = 1; off < 32; off <<= 1) {
            int t = __shfl_up_sync(0xffffffffu, s, off);
            if (lane >= off) s += t;
        }
        if (lane == 31) warpsum[w] = s;
        __syncthreads();
        if (w == 0 && lane < 8) {
            int t = warpsum[lane];
            #pragma unroll
            for (int off = 1; off < 8; off <<= 1) {
                int u = __shfl_up_sync(0x000000ffu, t, off);
                if (lane >= off) t += u;
            }
            warpsum[lane] = t;
        }
        __syncthreads();
        int wbase = (w > 0) ? warpsum[w - 1] : 0;
        g_hist[e * NBLK + c + tid] = carry + wbase + s - v;   // exclusive
        int tot = warpsum[7];
        __syncthreads();
        carry += tot;
    }
    if (tid == 0) g_total[e] = carry;
}

// ============================================================================
// K3: mask + renormalized weights. One block per GEMM-block segment
// (512 assignments). Exact walk order: warp-level match_any rank + in-block
// cross-warp per-expert prefix + scanned segment base.
// ============================================================================
__global__ __launch_bounds__(512)
void k_mask(float* __restrict__ out) {
    __shared__ int cnt[16 * NEXP];
    const int blk  = blockIdx.x;
    const int tid  = threadIdx.x;
    const int lane = tid & 31;
    const int w    = tid >> 5;
    const int i    = blk * 512 + tid;

    cnt[tid] = 0;
    cnt[tid + 512] = 0;
    __syncthreads();

    int e = g_idx[i];
    unsigned peers = __match_any_sync(0xffffffffu, e);
    unsigned lt    = (1u << lane) - 1u;
    int rank = __popc(peers & lt);
    if ((peers & lt) == 0u) cnt[w * NEXP + e] = __popc(peers);
    __syncthreads();

    int base = 0;
    for (int w2 = 0; w2 < w; w2++) base += cnt[w2 * NEXP + e];

    int pos = g_hist[e * NBLK + blk] + base + rank;
    float m  = (pos < CAP) ? 1.0f : 0.0f;
    float mo = __shfl_xor_sync(0xffffffffu, m, 1);
    float wgt = g_w[i];
    out[NA + i]     = wgt * m / (m + mo + 1e-10f);   // top_k_weights
    out[2 * NA + i] = m;                             // capacity_mask
}

// ============================================================================
// K4: expert_counters (min(total, cap)) and num_dropped.
// ============================================================================
__global__ void k_stats(float* __restrict__ out) {
    __shared__ int sdrop[NEXP];
    int e    = threadIdx.x;
    int tot  = g_total[e];
    int kept = min(tot, CAP);
    out[3 * NA + e] = (float)kept;                   // expert_counters
    sdrop[e] = tot - kept;
    __syncthreads();
    if (e == 0) {
        int s = 0;
        #pragma unroll
        for (int i = 0; i < NEXP; i++) s += sdrop[i];
        out[3 * NA + NEXP] = (float)s;               // num_dropped
    }
}

// ============================================================================
extern "C" void kernel_launch(void* const* d_in, const int* in_sizes, int n_in,
                              void* d_out, int out_size) {
    const float* x = (const float*)d_in[0];   // [N, 1024]
    const float* W = (const float*)d_in[1];   // [1024, 64]
    float* out = (float*)d_out;

    k_gemm_top2<<<NBLK, NTHREADS>>>(x, W, out);
    k_scan<<<NEXP, 256>>>();
    k_mask<<<NBLK, 512>>>(out);
    k_stats<<<1, NEXP>>>(out);
}